// round 13
// baseline (speedup 1.0000x reference)
#include <cuda_runtime.h>
#include <cuda_fp16.h>
#include <cstdint>
#include <math.h>

#define Bsz 2
#define SEQ 2048
#define HID 1024
#define NH  16
#define HD  64
#define NR  9          // 2*MAXREL+1

// ---------------- scratch (__device__ globals, no allocation) ----------------
__device__ half g_xf[Bsz * SEQ * HID];       // X fp16 single  [M=4096, K=1024]
__device__ half g_c [Bsz * SEQ * HID];       // ctx fp16 single (written by attn)
__device__ half g_q [Bsz * NH * SEQ * HD];   // [b,h,s,d] single fp16
__device__ half g_k [Bsz * NH * SEQ * HD];
__device__ half g_v [Bsz * NH * SEQ * HD];
__device__ half g_w [3 * HID * HID];         // QKV weights [3072,1024]T single
__device__ half g_wo[HID * HID];             // Wo [N,K] single
__device__ float g_bcat[3 * HID];

// ---------------------------- PTX helpers -----------------------------------
__device__ __forceinline__ uint32_t smem_u32(const void* p) {
    uint32_t a;
    asm("{ .reg .u64 t; cvta.to.shared.u64 t, %1; cvt.u32.u64 %0, t; }"
        : "=r"(a) : "l"(p));
    return a;
}
__device__ __forceinline__ void ldsm4(uint32_t* r, uint32_t addr) {
    asm volatile("ldmatrix.sync.aligned.m8n8.x4.shared.b16 {%0,%1,%2,%3}, [%4];"
                 : "=r"(r[0]), "=r"(r[1]), "=r"(r[2]), "=r"(r[3]) : "r"(addr));
}
__device__ __forceinline__ void ldsm4t(uint32_t* r, uint32_t addr) {
    asm volatile("ldmatrix.sync.aligned.m8n8.x4.trans.shared.b16 {%0,%1,%2,%3}, [%4];"
                 : "=r"(r[0]), "=r"(r[1]), "=r"(r[2]), "=r"(r[3]) : "r"(addr));
}
__device__ __forceinline__ void mma16816(float* c, const uint32_t* a, const uint32_t* b) {
    asm volatile(
        "mma.sync.aligned.m16n8k16.row.col.f32.f16.f16.f32 "
        "{%0,%1,%2,%3}, {%4,%5,%6,%7}, {%8,%9}, {%0,%1,%2,%3};"
        : "+f"(c[0]), "+f"(c[1]), "+f"(c[2]), "+f"(c[3])
        : "r"(a[0]), "r"(a[1]), "r"(a[2]), "r"(a[3]), "r"(b[0]), "r"(b[1]));
}
__device__ __forceinline__ uint32_t packh(float hi, float lo) {
    uint32_t d;
    asm("cvt.rn.f16x2.f32 %0, %1, %2;" : "=r"(d) : "f"(hi), "f"(lo));
    return d;
}

#define CP_ASYNC16(dst, src) \
    asm volatile("cp.async.cg.shared.global [%0], [%1], 16;" :: "r"(dst), "l"(src))
#define CP_COMMIT() asm volatile("cp.async.commit_group;" ::: "memory")
#define CP_WAIT(n)  asm volatile("cp.async.wait_group %0;" :: "n"(n) : "memory")

// 128B rows, 8x16B chunks, XOR swizzle
__device__ __forceinline__ uint32_t asw(int r, int c) {
    return (uint32_t)(r * 128 + (((c ^ (r & 7)) & 7) << 4));
}

// ============================================================================
// fused prep: 4 weight transposes + X fp16 conversion + bias concat, ONE launch
// ============================================================================
__global__ __launch_bounds__(256)
void prep_all(const float* __restrict__ x,
              const float* __restrict__ Wq, const float* __restrict__ Wk,
              const float* __restrict__ Wv, const float* __restrict__ Wo,
              const float* __restrict__ bq, const float* __restrict__ bk,
              const float* __restrict__ bv)
{
    const int bid = blockIdx.x;
    const int tid = threadIdx.x;
    if (bid < 4096) {
        int w  = bid >> 10;
        int t  = bid & 1023;
        int bx = (t & 31) * 32, by = (t >> 5) * 32;
        const float* W = (w == 0) ? Wq : (w == 1) ? Wk : (w == 2) ? Wv : Wo;
        half* outT = (w == 3) ? g_wo : g_w + (size_t)w * 1024 * 1024;
        __shared__ float tt[32][33];
        int tx = tid & 31, ty = tid >> 5;
#pragma unroll
        for (int j = 0; j < 4; j++)
            tt[ty * 4 + j][tx] = W[(size_t)(by + ty * 4 + j) * 1024 + bx + tx];
        __syncthreads();
#pragma unroll
        for (int j = 0; j < 4; j++)
            outT[(size_t)(bx + ty * 4 + j) * 1024 + by + tx] =
                __float2half_rn(tt[tx][ty * 4 + j]);
    } else if (bid < 5120) {
        const int n2 = Bsz * SEQ * HID / 2;
        for (int i = (bid - 4096) * 256 + tid; i < n2; i += 1024 * 256) {
            float2 v = ((const float2*)x)[i];
            ((__half2*)g_xf)[i] =
                __halves2half2(__float2half_rn(v.x), __float2half_rn(v.y));
        }
    } else {
        for (int i = tid; i < 1024; i += 256) {
            g_bcat[i] = bq[i];
            g_bcat[1024 + i] = bk[i];
            g_bcat[2048 + i] = bv[i];
        }
    }
}

// ============================================================================
// HMMA fp16 single-product GEMM:  C[M,N] = A[M,1024] * B^T  (B stored [N,K])
// CTA 256x128, 8 warps (4x2), warp tile 64x64 -> 0.25 ldsm/mma.
// K chunk 64, 3-stage cp.async (48K/stage, 144K total), occ 1, regs ~216.
// OUT_MODE 0: fused QKV (N=3072) -> scatter single-fp16 q/k/v [b,h,s,d]
// OUT_MODE 3: plain fp32 out[M,1024] + bias
// ============================================================================
#define GSTAGE 49152
#define GEMM_SMEM (3 * GSTAGE)

template<int OUT_MODE>
__global__ __launch_bounds__(256, 1)
void gemm_mma(const half* __restrict__ A, const half* __restrict__ B,
              const float* __restrict__ bias, float* __restrict__ out)
{
    extern __shared__ char sm[];
    const uint32_t sbase = smem_u32(sm);

    const int tid   = threadIdx.x;
    const int wid   = tid >> 5;
    const int lane  = tid & 31;
    const int warpM = wid >> 1;        // 0..3  (64 rows each)
    const int warpN = wid & 1;         // 0..1  (64 cols each)
    const int bm = blockIdx.y * 256;
    const int bn = blockIdx.x * 128;

    // staging: 12 x 16B per thread per stage (A 256x64 = 32K | B 128x64 = 16K)
    const half* gsrc[12];
    uint32_t    sdst[12];
#pragma unroll
    for (int i = 0; i < 12; i++) {
        int gg = i * 256 + tid;
        int isB  = (gg >= 2048);
        int idx  = isB ? (gg - 2048) : gg;
        int r = idx >> 3, c = idx & 7;
        const half* base = isB ? B : A;
        int grow = (isB ? bn : bm) + r;
        gsrc[i] = base + (size_t)grow * 1024 + c * 8;
        sdst[i] = sbase + (isB ? 32768 : 0) + asw(r, c);
    }

    float acc[4][8][4];
#pragma unroll
    for (int mt = 0; mt < 4; mt++)
#pragma unroll
        for (int nt = 0; nt < 8; nt++)
#pragma unroll
            for (int k = 0; k < 4; k++) acc[mt][nt][k] = 0.f;

#pragma unroll
    for (int s = 0; s < 2; s++) {
#pragma unroll
        for (int i = 0; i < 12; i++) CP_ASYNC16(sdst[i] + s * GSTAGE, gsrc[i] + s * 64);
        CP_COMMIT();
    }

    const int mrow  = warpM * 64 + (lane & 7) + ((lane >> 3) & 1) * 8;
    const int nrowp = warpN * 64 + (lane & 7) + ((lane >> 4) & 1) * 8;

    for (int kt = 0; kt < 16; kt++) {
        if (kt == 15) { CP_WAIT(0); } else { CP_WAIT(1); }
        __syncthreads();
        if (kt + 2 < 16) {
            int st = (kt + 2) % 3;
#pragma unroll
            for (int i = 0; i < 12; i++)
                CP_ASYNC16(sdst[i] + st * GSTAGE, gsrc[i] + (kt + 2) * 64);
            CP_COMMIT();
        }

        const uint32_t s0 = sbase + (kt % 3) * GSTAGE;
#pragma unroll
        for (int ks = 0; ks < 4; ks++) {
            uint32_t aS[4][4], bb[4][4];
            const int ac = ks * 2 + (lane >> 4);
#pragma unroll
            for (int mt = 0; mt < 4; mt++) {
                int m = mrow + mt * 16;
                ldsm4(aS[mt], s0 + asw(m, ac));
            }
            const int bc = ks * 2 + ((lane >> 3) & 1);
#pragma unroll
            for (int p = 0; p < 4; p++) {
                int n = nrowp + p * 16;
                ldsm4(bb[p], s0 + 32768 + asw(n, bc));
            }
#pragma unroll
            for (int mt = 0; mt < 4; mt++)
#pragma unroll
                for (int p = 0; p < 4; p++) {
                    mma16816(acc[mt][2 * p],     aS[mt], bb[p]);
                    mma16816(acc[mt][2 * p + 1], aS[mt], bb[p] + 2);
                }
        }
    }

    // ---- epilogue ----
#pragma unroll
    for (int mt = 0; mt < 4; mt++) {
#pragma unroll
        for (int nt = 0; nt < 8; nt++) {
            int r0 = bm + warpM * 64 + mt * 16 + (lane >> 2);
            int c0 = bn + warpN * 64 + nt * 8 + (lane & 3) * 2;
#pragma unroll
            for (int half_ = 0; half_ < 2; half_++) {
                int r = r0 + half_ * 8;
                float v0 = acc[mt][nt][half_ * 2 + 0] + bias[c0];
                float v1 = acc[mt][nt][half_ * 2 + 1] + bias[c0 + 1];
                if (OUT_MODE == 3) {
                    *(float2*)(out + (size_t)r * 1024 + c0) = make_float2(v0, v1);
                } else {
                    int b = r >> 11, s = r & 2047;
                    int hidx = c0 >> 6;
                    int which = hidx >> 4;
                    int h = hidx & 15;
                    int d = c0 & 63;
                    size_t idx = (((size_t)(b * NH + h)) * SEQ + s) * HD + d;
                    half* dst = (which == 0) ? g_q : (which == 1) ? g_k : g_v;
                    *(uint32_t*)(dst + idx) = packh(v1, v0);
                }
            }
        }
    }
}

// ============================================================================
// HMMA fp16 flash attention (unchanged from R12): 4-stage, 1 barrier / 2 tiles.
// ============================================================================
#define ASTGSZ 16384
#define AQ     (3 * ASTGSZ)   // Q prologue region = stage 3
#define AQREL  65536          // 128*9 f32
#define ATV    70144          // 9*64 f32
#define ATK    72448          // 9*64 f32
#define ATTN_SMEM 74752

__global__ __launch_bounds__(256, 2)
void attn_mma(const float* __restrict__ tkg, const float* __restrict__ tvg)
{
    extern __shared__ char sm[];
    const uint32_t sb = smem_u32(sm);
    float* qrel_s = (float*)(sm + AQREL);
    float* tv_s   = (float*)(sm + ATV);
    float* tk_s   = (float*)(sm + ATK);

    const int tid  = threadIdx.x;
    const int lane = tid & 31;
    const int w    = tid >> 5;
    const int bh   = blockIdx.y;
    const int q0   = blockIdx.x * 128;
    const size_t bhoff = (size_t)bh * SEQ * HD;

#pragma unroll
    for (int i = 0; i < 4; i++) {
        int g = i * 256 + tid;
        int r = g >> 3, c = g & 7;
        CP_ASYNC16(sb + AQ + asw(r, c), g_q + bhoff + (size_t)(q0 + r) * HD + c * 8);
    }
    CP_COMMIT();
#pragma unroll
    for (int st = 0; st < 2; st++) {
#pragma unroll
        for (int i = 0; i < 4; i++) {
            int g = i * 256 + tid;
            int tile = g >> 9;              // 0 K, 1 V
            int idx = g & 511;
            int r = idx >> 3, c = idx & 7;
            const half* src = (tile == 0 ? g_k : g_v)
                + bhoff + (size_t)(st * 64 + r) * HD + c * 8;
            CP_ASYNC16(sb + st * ASTGSZ + tile * 8192 + asw(r, c), src);
        }
        CP_COMMIT();
    }
    for (int i = tid; i < NR * 64; i += 256) { tk_s[i] = tkg[i]; tv_s[i] = tvg[i]; }

    CP_WAIT(2);
    __syncthreads();

    if (tid < 128) {
        int row = tid;
        float acc[NR];
#pragma unroll
        for (int r9 = 0; r9 < NR; r9++) acc[r9] = 0.f;
        for (int d = 0; d < 64; d++) {
            float q = __half2float(*(const half*)(sm + AQ + asw(row, d >> 3) + (d & 7) * 2));
#pragma unroll
            for (int r9 = 0; r9 < NR; r9++) acc[r9] += q * tk_s[r9 * 64 + d];
        }
#pragma unroll
        for (int r9 = 0; r9 < NR; r9++) qrel_s[row * NR + r9] = acc[r9];
    }
    __syncthreads();

    uint32_t qf[4][4];
#pragma unroll
    for (int ks = 0; ks < 4; ks++) {
        int r = w * 16 + (lane & 7) + ((lane >> 3) & 1) * 8;
        int c = ks * 2 + (lane >> 4);
        ldsm4(qf[ks], sb + AQ + asw(r, c));
    }

    const int row0 = w * 16 + (lane >> 2);
    const int row1 = row0 + 8;
    const float qA0 = qrel_s[row0 * NR + 0], qA8 = qrel_s[row0 * NR + 8];
    const float qB0 = qrel_s[row1 * NR + 0], qB8 = qrel_s[row1 * NR + 8];

    float oacc[8][4];
#pragma unroll
    for (int nt = 0; nt < 8; nt++)
#pragma unroll
        for (int e = 0; e < 4; e++) oacc[nt][e] = 0.f;
    float brA[NR], brB[NR];
#pragma unroll
    for (int r9 = 0; r9 < NR; r9++) { brA[r9] = 0.f; brB[r9] = 0.f; }

    for (int j = 0; j < 16; j++) {
        __syncthreads();

        if (j < 15) {
#pragma unroll
            for (int t2 = 0; t2 < 2; t2++) {
                int t = 2 * j + 2 + t2;
                uint32_t stb = sb + (t & 3) * ASTGSZ;
#pragma unroll
                for (int i = 0; i < 4; i++) {
                    int g = i * 256 + tid;
                    int tile = g >> 9;
                    int idx = g & 511;
                    int r = idx >> 3, c = idx & 7;
                    const half* src = (tile == 0 ? g_k : g_v)
                        + bhoff + (size_t)(t * 64 + r) * HD + c * 8;
                    CP_ASYNC16(stb + tile * 8192 + asw(r, c), src);
                }
                CP_COMMIT();
            }
            CP_WAIT(2);
        } else {
            CP_WAIT(0);
        }

#pragma unroll
        for (int t2 = 0; t2 < 2; t2++) {
            const int kt = 2 * j + t2;
            const uint32_t stg = sb + (kt & 3) * ASTGSZ;

            float sacc[8][4];
#pragma unroll
            for (int nt = 0; nt < 8; nt++)
#pragma unroll
                for (int e = 0; e < 4; e++) sacc[nt][e] = 0.f;

#pragma unroll
            for (int ks = 0; ks < 4; ks++) {
#pragma unroll
                for (int ntp = 0; ntp < 4; ntp++) {
                    uint32_t bK[4];
                    int r = ntp * 16 + (lane & 7) + ((lane >> 4) << 3);
                    int c = ks * 2 + ((lane >> 3) & 1);
                    ldsm4(bK, stg + asw(r, c));
                    mma16816(sacc[2 * ntp],     qf[ks], bK);
                    mma16816(sacc[2 * ntp + 1], qf[ks], bK + 2);
                }
            }

            const int k64 = kt * 64;
            bool hi_far = (k64 >= q0 + 131);
            bool lo_far = (k64 + 67 <= q0);
            if (hi_far || lo_far) {
                float biasA = hi_far ? qA8 : qA0;
                float biasB = hi_far ? qB8 : qB0;
                float sA = 0.f, sB = 0.f;
#pragma unroll
                for (int nt = 0; nt < 8; nt++) {
#pragma unroll
                    for (int e = 0; e < 4; e++) {
                        float p = __expf((sacc[nt][e] + (e < 2 ? biasA : biasB)) * 0.125f);
                        sacc[nt][e] = p;
                        if (e < 2) sA += p; else sB += p;
                    }
                }
                if (hi_far) { brA[8] += sA; brB[8] += sB; }
                else        { brA[0] += sA; brB[0] += sB; }
            } else {
#pragma unroll
                for (int nt = 0; nt < 8; nt++) {
#pragma unroll
                    for (int e = 0; e < 4; e++) {
                        int row = (e < 2) ? row0 : row1;
                        int col = nt * 8 + ((lane & 3) << 1) + (e & 1);
                        int rel = k64 + col - (q0 + row);
                        int bucket = min(max(rel, -4), 4) + 4;
                        float p = __expf((sacc[nt][e] + qrel_s[row * NR + bucket]) * 0.125f);
                        sacc[nt][e] = p;
                        float* br = (e < 2) ? brA : brB;
#pragma unroll
                        for (int r9 = 0; r9 < NR; r9++)
                            br[r9] += (bucket == r9) ? p : 0.f;
                    }
                }
            }

            uint32_t pf[4][4];
#pragma unroll
            for (int ks = 0; ks < 4; ks++) {
#pragma unroll
                for (int t = 0; t < 2; t++) {
                    pf[ks][2 * t]     = packh(sacc[2 * ks + t][1], sacc[2 * ks + t][0]);
                    pf[ks][2 * t + 1] = packh(sacc[2 * ks + t][3], sacc[2 * ks + t][2]);
                }
            }

#pragma unroll
            for (int ks = 0; ks < 4; ks++) {
#pragma unroll
                for (int ntp = 0; ntp < 4; ntp++) {
                    uint32_t vS[4];
                    int r = ks * 16 + (lane & 7) + ((lane >> 3) & 1) * 8;
                    int c = ntp * 2 + (lane >> 4);
                    ldsm4t(vS, stg + 8192 + asw(r, c));
                    mma16816(oacc[2 * ntp],     pf[ks], vS);
                    mma16816(oacc[2 * ntp + 1], pf[ks], vS + 2);
                }
            }
        }
    }

#pragma unroll
    for (int m = 1; m <= 2; m <<= 1) {
#pragma unroll
        for (int r9 = 0; r9 < NR; r9++) {
            brA[r9] += __shfl_xor_sync(0xffffffffu, brA[r9], m);
            brB[r9] += __shfl_xor_sync(0xffffffffu, brB[r9], m);
        }
    }
    float lA = 0.f, lB = 0.f;
#pragma unroll
    for (int r9 = 0; r9 < NR; r9++) { lA += brA[r9]; lB += brB[r9]; }
    const float iA = 1.f / lA, iB = 1.f / lB;

    const int b = bh >> 4, h = bh & 15;
    const size_t m0 = (size_t)(b * SEQ + q0 + row0) * HID + h * 64;
    const size_t m1 = (size_t)(b * SEQ + q0 + row1) * HID + h * 64;

#pragma unroll
    for (int nt = 0; nt < 8; nt++) {
        int d0 = nt * 8 + (lane & 3) * 2;
        float w00 = 0.f, w01 = 0.f, w10 = 0.f, w11 = 0.f;
#pragma unroll
        for (int r9 = 0; r9 < NR; r9++) {
            float2 t2 = *(const float2*)(tv_s + r9 * 64 + d0);
            w00 += brA[r9] * t2.x; w01 += brA[r9] * t2.y;
            w10 += brB[r9] * t2.x; w11 += brB[r9] * t2.y;
        }
        float v00 = (oacc[nt][0] + w00) * iA, v01 = (oacc[nt][1] + w01) * iA;
        float v10 = (oacc[nt][2] + w10) * iB, v11 = (oacc[nt][3] + w11) * iB;

        *(uint32_t*)(g_c + m0 + d0) = packh(v01, v00);
        *(uint32_t*)(g_c + m1 + d0) = packh(v11, v10);
    }
}

// ============================================================================
extern "C" void kernel_launch(void* const* d_in, const int* in_sizes, int n_in,
                              void* d_out, int out_size)
{
    const float* x  = (const float*)d_in[0];
    const float* Wq = (const float*)d_in[1];
    const float* bq = (const float*)d_in[2];
    const float* Wk = (const float*)d_in[3];
    const float* bk = (const float*)d_in[4];
    const float* Wv = (const float*)d_in[5];
    const float* bv = (const float*)d_in[6];
    const float* Wo = (const float*)d_in[7];
    const float* bo = (const float*)d_in[8];
    const float* tk = (const float*)d_in[9];
    const float* tv = (const float*)d_in[10];
    float* out = (float*)d_out;

    half *xf, *cc, *wc, *wo;
    float* bcat;
    cudaGetSymbolAddress((void**)&xf,  g_xf);
    cudaGetSymbolAddress((void**)&cc,  g_c);
    cudaGetSymbolAddress((void**)&wc,  g_w);
    cudaGetSymbolAddress((void**)&wo,  g_wo);
    cudaGetSymbolAddress((void**)&bcat, g_bcat);

    cudaFuncSetAttribute(gemm_mma<0>, cudaFuncAttributeMaxDynamicSharedMemorySize, GEMM_SMEM);
    cudaFuncSetAttribute(gemm_mma<3>, cudaFuncAttributeMaxDynamicSharedMemorySize, GEMM_SMEM);
    cudaFuncSetAttribute(attn_mma,    cudaFuncAttributeMaxDynamicSharedMemorySize, ATTN_SMEM);

    // 1. fused prep
    prep_all<<<5121, 256>>>(x, Wq, Wk, Wv, Wo, bq, bk, bv);

    // 2. fused QKV projection (M 4096 / 256 = 16, N 3072 / 128 = 24)
    gemm_mma<0><<<dim3(24, 16), 256, GEMM_SMEM>>>(xf, wc, bcat, nullptr);

    // 3. flash attention (4-stage, 1 barrier / 2 tiles)
    attn_mma<<<dim3(SEQ / 128, Bsz * NH), 256, ATTN_SMEM>>>(tk, tv);

    // 4. output projection (M 4096 / 256 = 16, N 1024 / 128 = 8)
    gemm_mma<3><<<dim3(8, 16), 256, GEMM_SMEM>>>(cc, wo, bo, out);
}

// round 14
// speedup vs baseline: 1.0072x; 1.0072x over previous
#include <cuda_runtime.h>
#include <cuda_fp16.h>
#include <cstdint>
#include <math.h>

#define Bsz 2
#define SEQ 2048
#define HID 1024
#define NH  16
#define HD  64
#define NR  9          // 2*MAXREL+1

// ---------------- scratch (__device__ globals, no allocation) ----------------
__device__ half g_xf[Bsz * SEQ * HID];       // X fp16 single  [M=4096, K=1024]
__device__ half g_c [Bsz * SEQ * HID];       // ctx fp16 single (written by attn)
__device__ half g_q [Bsz * NH * SEQ * HD];   // [b,h,s,d] single fp16
__device__ half g_k [Bsz * NH * SEQ * HD];
__device__ half g_v [Bsz * NH * SEQ * HD];
__device__ half g_w [3 * HID * HID];         // QKV weights [3072,1024]T single
__device__ half g_wo[HID * HID];             // Wo [N,K] single
__device__ float g_bcat[3 * HID];

// ---------------------------- PTX helpers -----------------------------------
__device__ __forceinline__ uint32_t smem_u32(const void* p) {
    uint32_t a;
    asm("{ .reg .u64 t; cvta.to.shared.u64 t, %1; cvt.u32.u64 %0, t; }"
        : "=r"(a) : "l"(p));
    return a;
}
__device__ __forceinline__ void ldsm4(uint32_t* r, uint32_t addr) {
    asm volatile("ldmatrix.sync.aligned.m8n8.x4.shared.b16 {%0,%1,%2,%3}, [%4];"
                 : "=r"(r[0]), "=r"(r[1]), "=r"(r[2]), "=r"(r[3]) : "r"(addr));
}
__device__ __forceinline__ void ldsm4t(uint32_t* r, uint32_t addr) {
    asm volatile("ldmatrix.sync.aligned.m8n8.x4.trans.shared.b16 {%0,%1,%2,%3}, [%4];"
                 : "=r"(r[0]), "=r"(r[1]), "=r"(r[2]), "=r"(r[3]) : "r"(addr));
}
__device__ __forceinline__ void mma16816(float* c, const uint32_t* a, const uint32_t* b) {
    asm volatile(
        "mma.sync.aligned.m16n8k16.row.col.f32.f16.f16.f32 "
        "{%0,%1,%2,%3}, {%4,%5,%6,%7}, {%8,%9}, {%0,%1,%2,%3};"
        : "+f"(c[0]), "+f"(c[1]), "+f"(c[2]), "+f"(c[3])
        : "r"(a[0]), "r"(a[1]), "r"(a[2]), "r"(a[3]), "r"(b[0]), "r"(b[1]));
}
// fp16-accumulator variant: d/c are 2 packed f16x2 regs
__device__ __forceinline__ void mma16816h(uint32_t* c, const uint32_t* a, const uint32_t* b) {
    asm volatile(
        "mma.sync.aligned.m16n8k16.row.col.f16.f16.f16.f16 "
        "{%0,%1}, {%2,%3,%4,%5}, {%6,%7}, {%0,%1};"
        : "+r"(c[0]), "+r"(c[1])
        : "r"(a[0]), "r"(a[1]), "r"(a[2]), "r"(a[3]), "r"(b[0]), "r"(b[1]));
}
__device__ __forceinline__ uint32_t packh(float hi, float lo) {
    uint32_t d;
    asm("cvt.rn.f16x2.f32 %0, %1, %2;" : "=r"(d) : "f"(hi), "f"(lo));
    return d;
}

#define CP_ASYNC16(dst, src) \
    asm volatile("cp.async.cg.shared.global [%0], [%1], 16;" :: "r"(dst), "l"(src))
#define CP_COMMIT() asm volatile("cp.async.commit_group;" ::: "memory")
#define CP_WAIT(n)  asm volatile("cp.async.wait_group %0;" :: "n"(n) : "memory")

// 128B rows, 8x16B chunks, XOR swizzle
__device__ __forceinline__ uint32_t asw(int r, int c) {
    return (uint32_t)(r * 128 + (((c ^ (r & 7)) & 7) << 4));
}

// ============================================================================
// fused prep: 4 weight transposes + X fp16 conversion + bias concat, ONE launch
// ============================================================================
__global__ __launch_bounds__(256)
void prep_all(const float* __restrict__ x,
              const float* __restrict__ Wq, const float* __restrict__ Wk,
              const float* __restrict__ Wv, const float* __restrict__ Wo,
              const float* __restrict__ bq, const float* __restrict__ bk,
              const float* __restrict__ bv)
{
    const int bid = blockIdx.x;
    const int tid = threadIdx.x;
    if (bid < 4096) {
        int w  = bid >> 10;
        int t  = bid & 1023;
        int bx = (t & 31) * 32, by = (t >> 5) * 32;
        const float* W = (w == 0) ? Wq : (w == 1) ? Wk : (w == 2) ? Wv : Wo;
        half* outT = (w == 3) ? g_wo : g_w + (size_t)w * 1024 * 1024;
        __shared__ float tt[32][33];
        int tx = tid & 31, ty = tid >> 5;
#pragma unroll
        for (int j = 0; j < 4; j++)
            tt[ty * 4 + j][tx] = W[(size_t)(by + ty * 4 + j) * 1024 + bx + tx];
        __syncthreads();
#pragma unroll
        for (int j = 0; j < 4; j++)
            outT[(size_t)(bx + ty * 4 + j) * 1024 + by + tx] =
                __float2half_rn(tt[tx][ty * 4 + j]);
    } else if (bid < 5120) {
        const int n2 = Bsz * SEQ * HID / 2;
        for (int i = (bid - 4096) * 256 + tid; i < n2; i += 1024 * 256) {
            float2 v = ((const float2*)x)[i];
            ((__half2*)g_xf)[i] =
                __halves2half2(__float2half_rn(v.x), __float2half_rn(v.y));
        }
    } else {
        for (int i = tid; i < 1024; i += 256) {
            g_bcat[i] = bq[i];
            g_bcat[1024 + i] = bk[i];
            g_bcat[2048 + i] = bv[i];
        }
    }
}

// ============================================================================
// HMMA fp16 single-product GEMM (R12 geometry: CTA 128x128, occ 2, K chunk 64)
// ============================================================================
#define GSTAGE 32768
#define GEMM_SMEM (3 * GSTAGE)

template<int OUT_MODE>
__global__ __launch_bounds__(256, 2)
void gemm_mma(const half* __restrict__ A, const half* __restrict__ B,
              const float* __restrict__ bias, float* __restrict__ out)
{
    extern __shared__ char sm[];
    const uint32_t sbase = smem_u32(sm);

    const int tid   = threadIdx.x;
    const int wid   = tid >> 5;
    const int lane  = tid & 31;
    const int warpM = wid >> 2;
    const int warpN = wid & 3;
    const int bm = blockIdx.y * 128;
    const int bn = blockIdx.x * 128;

    const half* gsrc[8];
    uint32_t    sdst[8];
#pragma unroll
    for (int i = 0; i < 8; i++) {
        int gg = i * 256 + tid;
        int tile = gg >> 10;
        int idx  = gg & 1023;
        int r = idx >> 3, c = idx & 7;
        const half* base = (tile == 0) ? A : B;
        int grow = ((tile == 0) ? bm : bn) + r;
        gsrc[i] = base + (size_t)grow * 1024 + c * 8;
        sdst[i] = sbase + tile * 16384 + asw(r, c);
    }

    float acc[4][4][4];
#pragma unroll
    for (int mt = 0; mt < 4; mt++)
#pragma unroll
        for (int nt = 0; nt < 4; nt++)
#pragma unroll
            for (int k = 0; k < 4; k++) acc[mt][nt][k] = 0.f;

#pragma unroll
    for (int s = 0; s < 2; s++) {
#pragma unroll
        for (int i = 0; i < 8; i++) CP_ASYNC16(sdst[i] + s * GSTAGE, gsrc[i] + s * 64);
        CP_COMMIT();
    }

    const int mrow = warpM * 64 + (lane & 7) + ((lane >> 3) & 1) * 8;
    const int nrowp = warpN * 32 + (lane & 7) + ((lane >> 4) & 1) * 8;

    for (int kt = 0; kt < 16; kt++) {
        if (kt == 15) { CP_WAIT(0); } else { CP_WAIT(1); }
        __syncthreads();
        if (kt + 2 < 16) {
            int st = (kt + 2) % 3;
#pragma unroll
            for (int i = 0; i < 8; i++)
                CP_ASYNC16(sdst[i] + st * GSTAGE, gsrc[i] + (kt + 2) * 64);
            CP_COMMIT();
        }

        const uint32_t s0 = sbase + (kt % 3) * GSTAGE;
#pragma unroll
        for (int ks = 0; ks < 4; ks++) {
            uint32_t aS[4][4], bb[2][4];
            const int ac = ks * 2 + (lane >> 4);
#pragma unroll
            for (int mt = 0; mt < 4; mt++) {
                int m = mrow + mt * 16;
                ldsm4(aS[mt], s0 + asw(m, ac));
            }
            const int bc = ks * 2 + ((lane >> 3) & 1);
#pragma unroll
            for (int p = 0; p < 2; p++) {
                int n = nrowp + p * 16;
                ldsm4(bb[p], s0 + 16384 + asw(n, bc));
            }
#pragma unroll
            for (int mt = 0; mt < 4; mt++)
#pragma unroll
                for (int p = 0; p < 2; p++) {
                    mma16816(acc[mt][2 * p],     aS[mt], bb[p]);
                    mma16816(acc[mt][2 * p + 1], aS[mt], bb[p] + 2);
                }
        }
    }

#pragma unroll
    for (int mt = 0; mt < 4; mt++) {
#pragma unroll
        for (int nt = 0; nt < 4; nt++) {
            int r0 = bm + warpM * 64 + mt * 16 + (lane >> 2);
            int c0 = bn + warpN * 32 + nt * 8 + (lane & 3) * 2;
#pragma unroll
            for (int half_ = 0; half_ < 2; half_++) {
                int r = r0 + half_ * 8;
                float v0 = acc[mt][nt][half_ * 2 + 0] + bias[c0];
                float v1 = acc[mt][nt][half_ * 2 + 1] + bias[c0 + 1];
                if (OUT_MODE == 3) {
                    *(float2*)(out + (size_t)r * 1024 + c0) = make_float2(v0, v1);
                } else {
                    int b = r >> 11, s = r & 2047;
                    int hidx = c0 >> 6;
                    int which = hidx >> 4;
                    int h = hidx & 15;
                    int d = c0 & 63;
                    size_t idx = (((size_t)(b * NH + h)) * SEQ + s) * HD + d;
                    half* dst = (which == 0) ? g_q : (which == 1) ? g_k : g_v;
                    *(uint32_t*)(dst + idx) = packh(v1, v0);
                }
            }
        }
    }
}

// ============================================================================
// HMMA fp16 flash attention: S-phase uses fp16 ACCUMULATORS (rate probe),
// PV stays fp32-acc.  4-stage pipeline, 1 barrier / 2 tiles (R12 structure).
// ============================================================================
#define ASTGSZ 16384
#define AQ     (3 * ASTGSZ)
#define AQREL  65536
#define ATV    70144
#define ATK    72448
#define ATTN_SMEM 74752

__global__ __launch_bounds__(256, 2)
void attn_mma(const float* __restrict__ tkg, const float* __restrict__ tvg)
{
    extern __shared__ char sm[];
    const uint32_t sb = smem_u32(sm);
    float* qrel_s = (float*)(sm + AQREL);
    float* tv_s   = (float*)(sm + ATV);
    float* tk_s   = (float*)(sm + ATK);

    const int tid  = threadIdx.x;
    const int lane = tid & 31;
    const int w    = tid >> 5;
    const int bh   = blockIdx.y;
    const int q0   = blockIdx.x * 128;
    const size_t bhoff = (size_t)bh * SEQ * HD;

#pragma unroll
    for (int i = 0; i < 4; i++) {
        int g = i * 256 + tid;
        int r = g >> 3, c = g & 7;
        CP_ASYNC16(sb + AQ + asw(r, c), g_q + bhoff + (size_t)(q0 + r) * HD + c * 8);
    }
    CP_COMMIT();
#pragma unroll
    for (int st = 0; st < 2; st++) {
#pragma unroll
        for (int i = 0; i < 4; i++) {
            int g = i * 256 + tid;
            int tile = g >> 9;
            int idx = g & 511;
            int r = idx >> 3, c = idx & 7;
            const half* src = (tile == 0 ? g_k : g_v)
                + bhoff + (size_t)(st * 64 + r) * HD + c * 8;
            CP_ASYNC16(sb + st * ASTGSZ + tile * 8192 + asw(r, c), src);
        }
        CP_COMMIT();
    }
    for (int i = tid; i < NR * 64; i += 256) { tk_s[i] = tkg[i]; tv_s[i] = tvg[i]; }

    CP_WAIT(2);
    __syncthreads();

    if (tid < 128) {
        int row = tid;
        float acc[NR];
#pragma unroll
        for (int r9 = 0; r9 < NR; r9++) acc[r9] = 0.f;
        for (int d = 0; d < 64; d++) {
            float q = __half2float(*(const half*)(sm + AQ + asw(row, d >> 3) + (d & 7) * 2));
#pragma unroll
            for (int r9 = 0; r9 < NR; r9++) acc[r9] += q * tk_s[r9 * 64 + d];
        }
#pragma unroll
        for (int r9 = 0; r9 < NR; r9++) qrel_s[row * NR + r9] = acc[r9];
    }
    __syncthreads();

    uint32_t qf[4][4];
#pragma unroll
    for (int ks = 0; ks < 4; ks++) {
        int r = w * 16 + (lane & 7) + ((lane >> 3) & 1) * 8;
        int c = ks * 2 + (lane >> 4);
        ldsm4(qf[ks], sb + AQ + asw(r, c));
    }

    const int row0 = w * 16 + (lane >> 2);
    const int row1 = row0 + 8;
    const float qA0 = qrel_s[row0 * NR + 0], qA8 = qrel_s[row0 * NR + 8];
    const float qB0 = qrel_s[row1 * NR + 0], qB8 = qrel_s[row1 * NR + 8];

    float oacc[8][4];
#pragma unroll
    for (int nt = 0; nt < 8; nt++)
#pragma unroll
        for (int e = 0; e < 4; e++) oacc[nt][e] = 0.f;
    float brA[NR], brB[NR];
#pragma unroll
    for (int r9 = 0; r9 < NR; r9++) { brA[r9] = 0.f; brB[r9] = 0.f; }

    for (int j = 0; j < 16; j++) {
        __syncthreads();

        if (j < 15) {
#pragma unroll
            for (int t2 = 0; t2 < 2; t2++) {
                int t = 2 * j + 2 + t2;
                uint32_t stb = sb + (t & 3) * ASTGSZ;
#pragma unroll
                for (int i = 0; i < 4; i++) {
                    int g = i * 256 + tid;
                    int tile = g >> 9;
                    int idx = g & 511;
                    int r = idx >> 3, c = idx & 7;
                    const half* src = (tile == 0 ? g_k : g_v)
                        + bhoff + (size_t)(t * 64 + r) * HD + c * 8;
                    CP_ASYNC16(stb + tile * 8192 + asw(r, c), src);
                }
                CP_COMMIT();
            }
            CP_WAIT(2);
        } else {
            CP_WAIT(0);
        }

#pragma unroll
        for (int t2 = 0; t2 < 2; t2++) {
            const int kt = 2 * j + t2;
            const uint32_t stg = sb + (kt & 3) * ASTGSZ;

            // ---- S = Q K^T with fp16 accumulators (packed d regs) ----
            uint32_t spk[8][2];
#pragma unroll
            for (int nt = 0; nt < 8; nt++) { spk[nt][0] = 0u; spk[nt][1] = 0u; }

#pragma unroll
            for (int ks = 0; ks < 4; ks++) {
#pragma unroll
                for (int ntp = 0; ntp < 4; ntp++) {
                    uint32_t bK[4];
                    int r = ntp * 16 + (lane & 7) + ((lane >> 4) << 3);
                    int c = ks * 2 + ((lane >> 3) & 1);
                    ldsm4(bK, stg + asw(r, c));
                    mma16816h(spk[2 * ntp],     qf[ks], bK);
                    mma16816h(spk[2 * ntp + 1], qf[ks], bK + 2);
                }
            }
            // unpack to fp32
            float sacc[8][4];
#pragma unroll
            for (int nt = 0; nt < 8; nt++) {
                float2 lo = __half22float2(*(__half2*)&spk[nt][0]);
                float2 hi = __half22float2(*(__half2*)&spk[nt][1]);
                sacc[nt][0] = lo.x; sacc[nt][1] = lo.y;
                sacc[nt][2] = hi.x; sacc[nt][3] = hi.y;
            }

            // ---- softmax + bucket sums ----
            const int k64 = kt * 64;
            bool hi_far = (k64 >= q0 + 131);
            bool lo_far = (k64 + 67 <= q0);
            if (hi_far || lo_far) {
                float biasA = hi_far ? qA8 : qA0;
                float biasB = hi_far ? qB8 : qB0;
                float sA = 0.f, sB = 0.f;
#pragma unroll
                for (int nt = 0; nt < 8; nt++) {
#pragma unroll
                    for (int e = 0; e < 4; e++) {
                        float p = __expf((sacc[nt][e] + (e < 2 ? biasA : biasB)) * 0.125f);
                        sacc[nt][e] = p;
                        if (e < 2) sA += p; else sB += p;
                    }
                }
                if (hi_far) { brA[8] += sA; brB[8] += sB; }
                else        { brA[0] += sA; brB[0] += sB; }
            } else {
#pragma unroll
                for (int nt = 0; nt < 8; nt++) {
#pragma unroll
                    for (int e = 0; e < 4; e++) {
                        int row = (e < 2) ? row0 : row1;
                        int col = nt * 8 + ((lane & 3) << 1) + (e & 1);
                        int rel = k64 + col - (q0 + row);
                        int bucket = min(max(rel, -4), 4) + 4;
                        float p = __expf((sacc[nt][e] + qrel_s[row * NR + bucket]) * 0.125f);
                        sacc[nt][e] = p;
                        float* br = (e < 2) ? brA : brB;
#pragma unroll
                        for (int r9 = 0; r9 < NR; r9++)
                            br[r9] += (bucket == r9) ? p : 0.f;
                    }
                }
            }

            // ---- convert P to fp16 A-fragments ----
            uint32_t pf[4][4];
#pragma unroll
            for (int ks = 0; ks < 4; ks++) {
#pragma unroll
                for (int t = 0; t < 2; t++) {
                    pf[ks][2 * t]     = packh(sacc[2 * ks + t][1], sacc[2 * ks + t][0]);
                    pf[ks][2 * t + 1] = packh(sacc[2 * ks + t][3], sacc[2 * ks + t][2]);
                }
            }

            // ---- O += P V (fp32 acc), V via ldmatrix.trans ----
#pragma unroll
            for (int ks = 0; ks < 4; ks++) {
#pragma unroll
                for (int ntp = 0; ntp < 4; ntp++) {
                    uint32_t vS[4];
                    int r = ks * 16 + (lane & 7) + ((lane >> 3) & 1) * 8;
                    int c = ntp * 2 + (lane >> 4);
                    ldsm4t(vS, stg + 8192 + asw(r, c));
                    mma16816(oacc[2 * ntp],     pf[ks], vS);
                    mma16816(oacc[2 * ntp + 1], pf[ks], vS + 2);
                }
            }
        }
    }

    // ---- epilogue ----
#pragma unroll
    for (int m = 1; m <= 2; m <<= 1) {
#pragma unroll
        for (int r9 = 0; r9 < NR; r9++) {
            brA[r9] += __shfl_xor_sync(0xffffffffu, brA[r9], m);
            brB[r9] += __shfl_xor_sync(0xffffffffu, brB[r9], m);
        }
    }
    float lA = 0.f, lB = 0.f;
#pragma unroll
    for (int r9 = 0; r9 < NR; r9++) { lA += brA[r9]; lB += brB[r9]; }
    const float iA = 1.f / lA, iB = 1.f / lB;

    const int b = bh >> 4, h = bh & 15;
    const size_t m0 = (size_t)(b * SEQ + q0 + row0) * HID + h * 64;
    const size_t m1 = (size_t)(b * SEQ + q0 + row1) * HID + h * 64;

#pragma unroll
    for (int nt = 0; nt < 8; nt++) {
        int d0 = nt * 8 + (lane & 3) * 2;
        float w00 = 0.f, w01 = 0.f, w10 = 0.f, w11 = 0.f;
#pragma unroll
        for (int r9 = 0; r9 < NR; r9++) {
            float2 t2 = *(const float2*)(tv_s + r9 * 64 + d0);
            w00 += brA[r9] * t2.x; w01 += brA[r9] * t2.y;
            w10 += brB[r9] * t2.x; w11 += brB[r9] * t2.y;
        }
        float v00 = (oacc[nt][0] + w00) * iA, v01 = (oacc[nt][1] + w01) * iA;
        float v10 = (oacc[nt][2] + w10) * iB, v11 = (oacc[nt][3] + w11) * iB;

        *(uint32_t*)(g_c + m0 + d0) = packh(v01, v00);
        *(uint32_t*)(g_c + m1 + d0) = packh(v11, v10);
    }
}

// ============================================================================
extern "C" void kernel_launch(void* const* d_in, const int* in_sizes, int n_in,
                              void* d_out, int out_size)
{
    const float* x  = (const float*)d_in[0];
    const float* Wq = (const float*)d_in[1];
    const float* bq = (const float*)d_in[2];
    const float* Wk = (const float*)d_in[3];
    const float* bk = (const float*)d_in[4];
    const float* Wv = (const float*)d_in[5];
    const float* bv = (const float*)d_in[6];
    const float* Wo = (const float*)d_in[7];
    const float* bo = (const float*)d_in[8];
    const float* tk = (const float*)d_in[9];
    const float* tv = (const float*)d_in[10];
    float* out = (float*)d_out;

    half *xf, *cc, *wc, *wo;
    float* bcat;
    cudaGetSymbolAddress((void**)&xf,  g_xf);
    cudaGetSymbolAddress((void**)&cc,  g_c);
    cudaGetSymbolAddress((void**)&wc,  g_w);
    cudaGetSymbolAddress((void**)&wo,  g_wo);
    cudaGetSymbolAddress((void**)&bcat, g_bcat);

    cudaFuncSetAttribute(gemm_mma<0>, cudaFuncAttributeMaxDynamicSharedMemorySize, GEMM_SMEM);
    cudaFuncSetAttribute(gemm_mma<3>, cudaFuncAttributeMaxDynamicSharedMemorySize, GEMM_SMEM);
    cudaFuncSetAttribute(attn_mma,    cudaFuncAttributeMaxDynamicSharedMemorySize, ATTN_SMEM);

    // 1. fused prep
    prep_all<<<5121, 256>>>(x, Wq, Wk, Wv, Wo, bq, bk, bv);

    // 2. fused QKV projection (N=3072)
    gemm_mma<0><<<dim3(24, 32), 256, GEMM_SMEM>>>(xf, wc, bcat, nullptr);

    // 3. flash attention (S-phase fp16-acc)
    attn_mma<<<dim3(SEQ / 128, Bsz * NH), 256, ATTN_SMEM>>>(tk, tv);

    // 4. output projection
    gemm_mma<3><<<dim3(8, 32), 256, GEMM_SMEM>>>(cc, wo, bo, out);
}

// round 15
// speedup vs baseline: 1.0213x; 1.0140x over previous
#include <cuda_runtime.h>
#include <cuda_fp16.h>
#include <cstdint>
#include <math.h>

#define Bsz 2
#define SEQ 2048
#define HID 1024
#define NH  16
#define HD  64
#define NR  9          // 2*MAXREL+1

// ---------------- scratch (__device__ globals, no allocation) ----------------
__device__ half g_xf[Bsz * SEQ * HID];       // X fp16 single  [M=4096, K=1024]
__device__ half g_c [Bsz * SEQ * HID];       // ctx fp16 single (written by attn)
__device__ half g_q [Bsz * NH * SEQ * HD];   // [b,h,s,d] single fp16
__device__ half g_k [Bsz * NH * SEQ * HD];
__device__ half g_v [Bsz * NH * SEQ * HD];
__device__ half g_w [3 * HID * HID];         // QKV weights [3072,1024]T single
__device__ half g_wo[HID * HID];             // Wo [N,K] single
__device__ float g_bcat[3 * HID];

// ---------------------------- PTX helpers -----------------------------------
__device__ __forceinline__ uint32_t smem_u32(const void* p) {
    uint32_t a;
    asm("{ .reg .u64 t; cvta.to.shared.u64 t, %1; cvt.u32.u64 %0, t; }"
        : "=r"(a) : "l"(p));
    return a;
}
__device__ __forceinline__ void ldsm4(uint32_t* r, uint32_t addr) {
    asm volatile("ldmatrix.sync.aligned.m8n8.x4.shared.b16 {%0,%1,%2,%3}, [%4];"
                 : "=r"(r[0]), "=r"(r[1]), "=r"(r[2]), "=r"(r[3]) : "r"(addr));
}
__device__ __forceinline__ void ldsm4t(uint32_t* r, uint32_t addr) {
    asm volatile("ldmatrix.sync.aligned.m8n8.x4.trans.shared.b16 {%0,%1,%2,%3}, [%4];"
                 : "=r"(r[0]), "=r"(r[1]), "=r"(r[2]), "=r"(r[3]) : "r"(addr));
}
__device__ __forceinline__ void mma16816(float* c, const uint32_t* a, const uint32_t* b) {
    asm volatile(
        "mma.sync.aligned.m16n8k16.row.col.f32.f16.f16.f32 "
        "{%0,%1,%2,%3}, {%4,%5,%6,%7}, {%8,%9}, {%0,%1,%2,%3};"
        : "+f"(c[0]), "+f"(c[1]), "+f"(c[2]), "+f"(c[3])
        : "r"(a[0]), "r"(a[1]), "r"(a[2]), "r"(a[3]), "r"(b[0]), "r"(b[1]));
}
__device__ __forceinline__ uint32_t packh(float hi, float lo) {
    uint32_t d;
    asm("cvt.rn.f16x2.f32 %0, %1, %2;" : "=r"(d) : "f"(hi), "f"(lo));
    return d;
}

#define CP_ASYNC16(dst, src) \
    asm volatile("cp.async.cg.shared.global [%0], [%1], 16;" :: "r"(dst), "l"(src))
#define CP_COMMIT() asm volatile("cp.async.commit_group;" ::: "memory")
#define CP_WAIT(n)  asm volatile("cp.async.wait_group %0;" :: "n"(n) : "memory")

// 128B rows, 8x16B chunks, XOR swizzle
__device__ __forceinline__ uint32_t asw(int r, int c) {
    return (uint32_t)(r * 128 + (((c ^ (r & 7)) & 7) << 4));
}

// ============================================================================
// fused prep (vectorized): 4 weight transposes (64x64 tiles, float4 in /
// uint4 out) + X fp16 conversion (float4/uint4) + bias concat.  grid 2049.
// ============================================================================
__global__ __launch_bounds__(256)
void prep_all(const float* __restrict__ x,
              const float* __restrict__ Wq, const float* __restrict__ Wk,
              const float* __restrict__ Wv, const float* __restrict__ Wo,
              const float* __restrict__ bq, const float* __restrict__ bk,
              const float* __restrict__ bv)
{
    const int bid = blockIdx.x;
    const int tid = threadIdx.x;
    if (bid < 1024) {
        // ---- weight transpose+convert: 64x64 tile per block ----
        int w  = bid >> 8;                 // 0..3
        int t  = bid & 255;
        int bx = (t & 15) * 64, by = (t >> 4) * 64;
        const float* W = (w == 0) ? Wq : (w == 1) ? Wk : (w == 2) ? Wv : Wo;
        half* outT = (w == 3) ? g_wo : g_w + (size_t)w * 1024 * 1024;
        __shared__ float tt[64][65];
        // load 64x64 floats via float4 (1024 float4, 4 per thread)
#pragma unroll
        for (int i = 0; i < 4; i++) {
            int idx = i * 256 + tid;
            int r = idx >> 4, c4 = idx & 15;
            float4 v = *(const float4*)(W + (size_t)(by + r) * 1024 + bx + c4 * 4);
            tt[r][c4 * 4 + 0] = v.x;
            tt[r][c4 * 4 + 1] = v.y;
            tt[r][c4 * 4 + 2] = v.z;
            tt[r][c4 * 4 + 3] = v.w;
        }
        __syncthreads();
        // store transposed: out[bx+n][by + k], 8 halves (uint4) per store
#pragma unroll
        for (int i = 0; i < 2; i++) {
            int idx = i * 256 + tid;       // 0..511
            int n = idx >> 3;              // 0..63
            int c8 = idx & 7;              // 8-k group
            uint32_t hp[4];
#pragma unroll
            for (int j = 0; j < 4; j++) {
                float f0 = tt[c8 * 8 + 2 * j + 0][n];
                float f1 = tt[c8 * 8 + 2 * j + 1][n];
                hp[j] = packh(f1, f0);
            }
            *(uint4*)(outT + (size_t)(bx + n) * 1024 + by + c8 * 8) =
                make_uint4(hp[0], hp[1], hp[2], hp[3]);
        }
    } else if (bid < 2048) {
        // ---- X fp32 -> fp16, 8 elems per thread per iter ----
        const int n8 = Bsz * SEQ * HID / 8;   // 524288
        for (int i = (bid - 1024) * 256 + tid; i < n8; i += 1024 * 256) {
            float4 a = ((const float4*)x)[2 * i];
            float4 b = ((const float4*)x)[2 * i + 1];
            ((uint4*)g_xf)[i] = make_uint4(packh(a.y, a.x), packh(a.w, a.z),
                                           packh(b.y, b.x), packh(b.w, b.z));
        }
    } else {
        // ---- bias concat ----
        for (int i = tid; i < 1024; i += 256) {
            g_bcat[i] = bq[i];
            g_bcat[1024 + i] = bk[i];
            g_bcat[2048 + i] = bv[i];
        }
    }
}

// ============================================================================
// HMMA fp16 single-product GEMM (R12 geometry: CTA 128x128, occ 2, K chunk 64)
// ============================================================================
#define GSTAGE 32768
#define GEMM_SMEM (3 * GSTAGE)

template<int OUT_MODE>
__global__ __launch_bounds__(256, 2)
void gemm_mma(const half* __restrict__ A, const half* __restrict__ B,
              const float* __restrict__ bias, float* __restrict__ out)
{
    extern __shared__ char sm[];
    const uint32_t sbase = smem_u32(sm);

    const int tid   = threadIdx.x;
    const int wid   = tid >> 5;
    const int lane  = tid & 31;
    const int warpM = wid >> 2;
    const int warpN = wid & 3;
    const int bm = blockIdx.y * 128;
    const int bn = blockIdx.x * 128;

    const half* gsrc[8];
    uint32_t    sdst[8];
#pragma unroll
    for (int i = 0; i < 8; i++) {
        int gg = i * 256 + tid;
        int tile = gg >> 10;
        int idx  = gg & 1023;
        int r = idx >> 3, c = idx & 7;
        const half* base = (tile == 0) ? A : B;
        int grow = ((tile == 0) ? bm : bn) + r;
        gsrc[i] = base + (size_t)grow * 1024 + c * 8;
        sdst[i] = sbase + tile * 16384 + asw(r, c);
    }

    float acc[4][4][4];
#pragma unroll
    for (int mt = 0; mt < 4; mt++)
#pragma unroll
        for (int nt = 0; nt < 4; nt++)
#pragma unroll
            for (int k = 0; k < 4; k++) acc[mt][nt][k] = 0.f;

#pragma unroll
    for (int s = 0; s < 2; s++) {
#pragma unroll
        for (int i = 0; i < 8; i++) CP_ASYNC16(sdst[i] + s * GSTAGE, gsrc[i] + s * 64);
        CP_COMMIT();
    }

    const int mrow = warpM * 64 + (lane & 7) + ((lane >> 3) & 1) * 8;
    const int nrowp = warpN * 32 + (lane & 7) + ((lane >> 4) & 1) * 8;

    for (int kt = 0; kt < 16; kt++) {
        if (kt == 15) { CP_WAIT(0); } else { CP_WAIT(1); }
        __syncthreads();
        if (kt + 2 < 16) {
            int st = (kt + 2) % 3;
#pragma unroll
            for (int i = 0; i < 8; i++)
                CP_ASYNC16(sdst[i] + st * GSTAGE, gsrc[i] + (kt + 2) * 64);
            CP_COMMIT();
        }

        const uint32_t s0 = sbase + (kt % 3) * GSTAGE;
#pragma unroll
        for (int ks = 0; ks < 4; ks++) {
            uint32_t aS[4][4], bb[2][4];
            const int ac = ks * 2 + (lane >> 4);
#pragma unroll
            for (int mt = 0; mt < 4; mt++) {
                int m = mrow + mt * 16;
                ldsm4(aS[mt], s0 + asw(m, ac));
            }
            const int bc = ks * 2 + ((lane >> 3) & 1);
#pragma unroll
            for (int p = 0; p < 2; p++) {
                int n = nrowp + p * 16;
                ldsm4(bb[p], s0 + 16384 + asw(n, bc));
            }
#pragma unroll
            for (int mt = 0; mt < 4; mt++)
#pragma unroll
                for (int p = 0; p < 2; p++) {
                    mma16816(acc[mt][2 * p],     aS[mt], bb[p]);
                    mma16816(acc[mt][2 * p + 1], aS[mt], bb[p] + 2);
                }
        }
    }

#pragma unroll
    for (int mt = 0; mt < 4; mt++) {
#pragma unroll
        for (int nt = 0; nt < 4; nt++) {
            int r0 = bm + warpM * 64 + mt * 16 + (lane >> 2);
            int c0 = bn + warpN * 32 + nt * 8 + (lane & 3) * 2;
#pragma unroll
            for (int half_ = 0; half_ < 2; half_++) {
                int r = r0 + half_ * 8;
                float v0 = acc[mt][nt][half_ * 2 + 0] + bias[c0];
                float v1 = acc[mt][nt][half_ * 2 + 1] + bias[c0 + 1];
                if (OUT_MODE == 3) {
                    *(float2*)(out + (size_t)r * 1024 + c0) = make_float2(v0, v1);
                } else {
                    int b = r >> 11, s = r & 2047;
                    int hidx = c0 >> 6;
                    int which = hidx >> 4;
                    int h = hidx & 15;
                    int d = c0 & 63;
                    size_t idx = (((size_t)(b * NH + h)) * SEQ + s) * HD + d;
                    half* dst = (which == 0) ? g_q : (which == 1) ? g_k : g_v;
                    *(uint32_t*)(dst + idx) = packh(v1, v0);
                }
            }
        }
    }
}

// ============================================================================
// HMMA fp16 flash attention (R12 structure: fp32 acc, 4-stage, 1 barrier / 2)
// ============================================================================
#define ASTGSZ 16384
#define AQ     (3 * ASTGSZ)
#define AQREL  65536
#define ATV    70144
#define ATK    72448
#define ATTN_SMEM 74752

__global__ __launch_bounds__(256, 2)
void attn_mma(const float* __restrict__ tkg, const float* __restrict__ tvg)
{
    extern __shared__ char sm[];
    const uint32_t sb = smem_u32(sm);
    float* qrel_s = (float*)(sm + AQREL);
    float* tv_s   = (float*)(sm + ATV);
    float* tk_s   = (float*)(sm + ATK);

    const int tid  = threadIdx.x;
    const int lane = tid & 31;
    const int w    = tid >> 5;
    const int bh   = blockIdx.y;
    const int q0   = blockIdx.x * 128;
    const size_t bhoff = (size_t)bh * SEQ * HD;

#pragma unroll
    for (int i = 0; i < 4; i++) {
        int g = i * 256 + tid;
        int r = g >> 3, c = g & 7;
        CP_ASYNC16(sb + AQ + asw(r, c), g_q + bhoff + (size_t)(q0 + r) * HD + c * 8);
    }
    CP_COMMIT();
#pragma unroll
    for (int st = 0; st < 2; st++) {
#pragma unroll
        for (int i = 0; i < 4; i++) {
            int g = i * 256 + tid;
            int tile = g >> 9;
            int idx = g & 511;
            int r = idx >> 3, c = idx & 7;
            const half* src = (tile == 0 ? g_k : g_v)
                + bhoff + (size_t)(st * 64 + r) * HD + c * 8;
            CP_ASYNC16(sb + st * ASTGSZ + tile * 8192 + asw(r, c), src);
        }
        CP_COMMIT();
    }
    for (int i = tid; i < NR * 64; i += 256) { tk_s[i] = tkg[i]; tv_s[i] = tvg[i]; }

    CP_WAIT(2);
    __syncthreads();

    if (tid < 128) {
        int row = tid;
        float acc[NR];
#pragma unroll
        for (int r9 = 0; r9 < NR; r9++) acc[r9] = 0.f;
        for (int d = 0; d < 64; d++) {
            float q = __half2float(*(const half*)(sm + AQ + asw(row, d >> 3) + (d & 7) * 2));
#pragma unroll
            for (int r9 = 0; r9 < NR; r9++) acc[r9] += q * tk_s[r9 * 64 + d];
        }
#pragma unroll
        for (int r9 = 0; r9 < NR; r9++) qrel_s[row * NR + r9] = acc[r9];
    }
    __syncthreads();

    uint32_t qf[4][4];
#pragma unroll
    for (int ks = 0; ks < 4; ks++) {
        int r = w * 16 + (lane & 7) + ((lane >> 3) & 1) * 8;
        int c = ks * 2 + (lane >> 4);
        ldsm4(qf[ks], sb + AQ + asw(r, c));
    }

    const int row0 = w * 16 + (lane >> 2);
    const int row1 = row0 + 8;
    const float qA0 = qrel_s[row0 * NR + 0], qA8 = qrel_s[row0 * NR + 8];
    const float qB0 = qrel_s[row1 * NR + 0], qB8 = qrel_s[row1 * NR + 8];

    float oacc[8][4];
#pragma unroll
    for (int nt = 0; nt < 8; nt++)
#pragma unroll
        for (int e = 0; e < 4; e++) oacc[nt][e] = 0.f;
    float brA[NR], brB[NR];
#pragma unroll
    for (int r9 = 0; r9 < NR; r9++) { brA[r9] = 0.f; brB[r9] = 0.f; }

    for (int j = 0; j < 16; j++) {
        __syncthreads();

        if (j < 15) {
#pragma unroll
            for (int t2 = 0; t2 < 2; t2++) {
                int t = 2 * j + 2 + t2;
                uint32_t stb = sb + (t & 3) * ASTGSZ;
#pragma unroll
                for (int i = 0; i < 4; i++) {
                    int g = i * 256 + tid;
                    int tile = g >> 9;
                    int idx = g & 511;
                    int r = idx >> 3, c = idx & 7;
                    const half* src = (tile == 0 ? g_k : g_v)
                        + bhoff + (size_t)(t * 64 + r) * HD + c * 8;
                    CP_ASYNC16(stb + tile * 8192 + asw(r, c), src);
                }
                CP_COMMIT();
            }
            CP_WAIT(2);
        } else {
            CP_WAIT(0);
        }

#pragma unroll
        for (int t2 = 0; t2 < 2; t2++) {
            const int kt = 2 * j + t2;
            const uint32_t stg = sb + (kt & 3) * ASTGSZ;

            float sacc[8][4];
#pragma unroll
            for (int nt = 0; nt < 8; nt++)
#pragma unroll
                for (int e = 0; e < 4; e++) sacc[nt][e] = 0.f;

#pragma unroll
            for (int ks = 0; ks < 4; ks++) {
#pragma unroll
                for (int ntp = 0; ntp < 4; ntp++) {
                    uint32_t bK[4];
                    int r = ntp * 16 + (lane & 7) + ((lane >> 4) << 3);
                    int c = ks * 2 + ((lane >> 3) & 1);
                    ldsm4(bK, stg + asw(r, c));
                    mma16816(sacc[2 * ntp],     qf[ks], bK);
                    mma16816(sacc[2 * ntp + 1], qf[ks], bK + 2);
                }
            }

            const int k64 = kt * 64;
            bool hi_far = (k64 >= q0 + 131);
            bool lo_far = (k64 + 67 <= q0);
            if (hi_far || lo_far) {
                float biasA = hi_far ? qA8 : qA0;
                float biasB = hi_far ? qB8 : qB0;
                float sA = 0.f, sB = 0.f;
#pragma unroll
                for (int nt = 0; nt < 8; nt++) {
#pragma unroll
                    for (int e = 0; e < 4; e++) {
                        float p = __expf((sacc[nt][e] + (e < 2 ? biasA : biasB)) * 0.125f);
                        sacc[nt][e] = p;
                        if (e < 2) sA += p; else sB += p;
                    }
                }
                if (hi_far) { brA[8] += sA; brB[8] += sB; }
                else        { brA[0] += sA; brB[0] += sB; }
            } else {
#pragma unroll
                for (int nt = 0; nt < 8; nt++) {
#pragma unroll
                    for (int e = 0; e < 4; e++) {
                        int row = (e < 2) ? row0 : row1;
                        int col = nt * 8 + ((lane & 3) << 1) + (e & 1);
                        int rel = k64 + col - (q0 + row);
                        int bucket = min(max(rel, -4), 4) + 4;
                        float p = __expf((sacc[nt][e] + qrel_s[row * NR + bucket]) * 0.125f);
                        sacc[nt][e] = p;
                        float* br = (e < 2) ? brA : brB;
#pragma unroll
                        for (int r9 = 0; r9 < NR; r9++)
                            br[r9] += (bucket == r9) ? p : 0.f;
                    }
                }
            }

            uint32_t pf[4][4];
#pragma unroll
            for (int ks = 0; ks < 4; ks++) {
#pragma unroll
                for (int t = 0; t < 2; t++) {
                    pf[ks][2 * t]     = packh(sacc[2 * ks + t][1], sacc[2 * ks + t][0]);
                    pf[ks][2 * t + 1] = packh(sacc[2 * ks + t][3], sacc[2 * ks + t][2]);
                }
            }

#pragma unroll
            for (int ks = 0; ks < 4; ks++) {
#pragma unroll
                for (int ntp = 0; ntp < 4; ntp++) {
                    uint32_t vS[4];
                    int r = ks * 16 + (lane & 7) + ((lane >> 3) & 1) * 8;
                    int c = ntp * 2 + (lane >> 4);
                    ldsm4t(vS, stg + 8192 + asw(r, c));
                    mma16816(oacc[2 * ntp],     pf[ks], vS);
                    mma16816(oacc[2 * ntp + 1], pf[ks], vS + 2);
                }
            }
        }
    }

#pragma unroll
    for (int m = 1; m <= 2; m <<= 1) {
#pragma unroll
        for (int r9 = 0; r9 < NR; r9++) {
            brA[r9] += __shfl_xor_sync(0xffffffffu, brA[r9], m);
            brB[r9] += __shfl_xor_sync(0xffffffffu, brB[r9], m);
        }
    }
    float lA = 0.f, lB = 0.f;
#pragma unroll
    for (int r9 = 0; r9 < NR; r9++) { lA += brA[r9]; lB += brB[r9]; }
    const float iA = 1.f / lA, iB = 1.f / lB;

    const int b = bh >> 4, h = bh & 15;
    const size_t m0 = (size_t)(b * SEQ + q0 + row0) * HID + h * 64;
    const size_t m1 = (size_t)(b * SEQ + q0 + row1) * HID + h * 64;

#pragma unroll
    for (int nt = 0; nt < 8; nt++) {
        int d0 = nt * 8 + (lane & 3) * 2;
        float w00 = 0.f, w01 = 0.f, w10 = 0.f, w11 = 0.f;
#pragma unroll
        for (int r9 = 0; r9 < NR; r9++) {
            float2 t2 = *(const float2*)(tv_s + r9 * 64 + d0);
            w00 += brA[r9] * t2.x; w01 += brA[r9] * t2.y;
            w10 += brB[r9] * t2.x; w11 += brB[r9] * t2.y;
        }
        float v00 = (oacc[nt][0] + w00) * iA, v01 = (oacc[nt][1] + w01) * iA;
        float v10 = (oacc[nt][2] + w10) * iB, v11 = (oacc[nt][3] + w11) * iB;

        *(uint32_t*)(g_c + m0 + d0) = packh(v01, v00);
        *(uint32_t*)(g_c + m1 + d0) = packh(v11, v10);
    }
}

// ============================================================================
extern "C" void kernel_launch(void* const* d_in, const int* in_sizes, int n_in,
                              void* d_out, int out_size)
{
    const float* x  = (const float*)d_in[0];
    const float* Wq = (const float*)d_in[1];
    const float* bq = (const float*)d_in[2];
    const float* Wk = (const float*)d_in[3];
    const float* bk = (const float*)d_in[4];
    const float* Wv = (const float*)d_in[5];
    const float* bv = (const float*)d_in[6];
    const float* Wo = (const float*)d_in[7];
    const float* bo = (const float*)d_in[8];
    const float* tk = (const float*)d_in[9];
    const float* tv = (const float*)d_in[10];
    float* out = (float*)d_out;

    half *xf, *cc, *wc, *wo;
    float* bcat;
    cudaGetSymbolAddress((void**)&xf,  g_xf);
    cudaGetSymbolAddress((void**)&cc,  g_c);
    cudaGetSymbolAddress((void**)&wc,  g_w);
    cudaGetSymbolAddress((void**)&wo,  g_wo);
    cudaGetSymbolAddress((void**)&bcat, g_bcat);

    cudaFuncSetAttribute(gemm_mma<0>, cudaFuncAttributeMaxDynamicSharedMemorySize, GEMM_SMEM);
    cudaFuncSetAttribute(gemm_mma<3>, cudaFuncAttributeMaxDynamicSharedMemorySize, GEMM_SMEM);
    cudaFuncSetAttribute(attn_mma,    cudaFuncAttributeMaxDynamicSharedMemorySize, ATTN_SMEM);

    // 1. fused prep (vectorized)
    prep_all<<<2049, 256>>>(x, Wq, Wk, Wv, Wo, bq, bk, bv);

    // 2. fused QKV projection (N=3072)
    gemm_mma<0><<<dim3(24, 32), 256, GEMM_SMEM>>>(xf, wc, bcat, nullptr);

    // 3. flash attention
    attn_mma<<<dim3(SEQ / 128, Bsz * NH), 256, ATTN_SMEM>>>(tk, tv);

    // 4. output projection
    gemm_mma<3><<<dim3(8, 32), 256, GEMM_SMEM>>>(cc, wo, bo, out);
}

// round 16
// speedup vs baseline: 1.0304x; 1.0089x over previous
#include <cuda_runtime.h>
#include <cuda_fp16.h>
#include <cstdint>
#include <math.h>

#define Bsz 2
#define SEQ 2048
#define HID 1024
#define NH  16
#define HD  64
#define NR  9          // 2*MAXREL+1

// ---------------- scratch (__device__ globals, no allocation) ----------------
__device__ half g_xf[Bsz * SEQ * HID];       // X fp16 single  [M=4096, K=1024]
__device__ half g_c [Bsz * SEQ * HID];       // ctx fp16 single (written by attn)
__device__ half g_q [Bsz * NH * SEQ * HD];   // [b,h,s,d] single fp16
__device__ half g_k [Bsz * NH * SEQ * HD];
__device__ half g_v [Bsz * NH * SEQ * HD];
__device__ half g_w [3 * HID * HID];         // QKV weights NATIVE [K,N] fp16, 3 blocks
__device__ half g_wo[HID * HID];             // Wo native [K,N] fp16
__device__ float g_bcat[3 * HID];

// ---------------------------- PTX helpers -----------------------------------
__device__ __forceinline__ uint32_t smem_u32(const void* p) {
    uint32_t a;
    asm("{ .reg .u64 t; cvta.to.shared.u64 t, %1; cvt.u32.u64 %0, t; }"
        : "=r"(a) : "l"(p));
    return a;
}
__device__ __forceinline__ void ldsm4(uint32_t* r, uint32_t addr) {
    asm volatile("ldmatrix.sync.aligned.m8n8.x4.shared.b16 {%0,%1,%2,%3}, [%4];"
                 : "=r"(r[0]), "=r"(r[1]), "=r"(r[2]), "=r"(r[3]) : "r"(addr));
}
__device__ __forceinline__ void ldsm4t(uint32_t* r, uint32_t addr) {
    asm volatile("ldmatrix.sync.aligned.m8n8.x4.trans.shared.b16 {%0,%1,%2,%3}, [%4];"
                 : "=r"(r[0]), "=r"(r[1]), "=r"(r[2]), "=r"(r[3]) : "r"(addr));
}
__device__ __forceinline__ void mma16816(float* c, const uint32_t* a, const uint32_t* b) {
    asm volatile(
        "mma.sync.aligned.m16n8k16.row.col.f32.f16.f16.f32 "
        "{%0,%1,%2,%3}, {%4,%5,%6,%7}, {%8,%9}, {%0,%1,%2,%3};"
        : "+f"(c[0]), "+f"(c[1]), "+f"(c[2]), "+f"(c[3])
        : "r"(a[0]), "r"(a[1]), "r"(a[2]), "r"(a[3]), "r"(b[0]), "r"(b[1]));
}
__device__ __forceinline__ uint32_t packh(float hi, float lo) {
    uint32_t d;
    asm("cvt.rn.f16x2.f32 %0, %1, %2;" : "=r"(d) : "f"(hi), "f"(lo));
    return d;
}

#define CP_ASYNC16(dst, src) \
    asm volatile("cp.async.cg.shared.global [%0], [%1], 16;" :: "r"(dst), "l"(src))
#define CP_COMMIT() asm volatile("cp.async.commit_group;" ::: "memory")
#define CP_WAIT(n)  asm volatile("cp.async.wait_group %0;" :: "n"(n) : "memory")

// 128B rows, 8x16B chunks, XOR swizzle
__device__ __forceinline__ uint32_t asw(int r, int c) {
    return (uint32_t)(r * 128 + (((c ^ (r & 7)) & 7) << 4));
}

// ============================================================================
// fused prep (pure streaming, no transpose): weights fp32->fp16 in native
// [K,N] layout + X conversion + bias concat.  grid 2049 x 256.
// ============================================================================
__global__ __launch_bounds__(256)
void prep_all(const float* __restrict__ x,
              const float* __restrict__ Wq, const float* __restrict__ Wk,
              const float* __restrict__ Wv, const float* __restrict__ Wo,
              const float* __restrict__ bq, const float* __restrict__ bk,
              const float* __restrict__ bv)
{
    const int bid = blockIdx.x;
    const int tid = threadIdx.x;
    if (bid < 1024) {
        // weights: 4 x 1M elems = 524288 uint4 total; 512 uint4 per block
        int base = bid * 512;
#pragma unroll
        for (int i = 0; i < 2; i++) {
            int g = base + i * 256 + tid;          // 0..524287
            int w = g >> 17;                       // 0..3
            int iw = g & 131071;                   // uint4 index within weight
            const float* W = (w == 0) ? Wq : (w == 1) ? Wk : (w == 2) ? Wv : Wo;
            half* dst = (w == 3) ? g_wo : g_w + (size_t)w * 1024 * 1024;
            float4 a = ((const float4*)W)[2 * iw];
            float4 b = ((const float4*)W)[2 * iw + 1];
            ((uint4*)dst)[iw] = make_uint4(packh(a.y, a.x), packh(a.w, a.z),
                                           packh(b.y, b.x), packh(b.w, b.z));
        }
    } else if (bid < 2048) {
        const int n8 = Bsz * SEQ * HID / 8;        // 524288
        for (int i = (bid - 1024) * 256 + tid; i < n8; i += 1024 * 256) {
            float4 a = ((const float4*)x)[2 * i];
            float4 b = ((const float4*)x)[2 * i + 1];
            ((uint4*)g_xf)[i] = make_uint4(packh(a.y, a.x), packh(a.w, a.z),
                                           packh(b.y, b.x), packh(b.w, b.z));
        }
    } else {
        for (int i = tid; i < 1024; i += 256) {
            g_bcat[i] = bq[i];
            g_bcat[1024 + i] = bk[i];
            g_bcat[2048 + i] = bv[i];
        }
    }
}

// ============================================================================
// HMMA fp16 GEMM with NATIVE [K,N] weights:  C[M,N] = A[M,1024] * W
// CTA 128x128, 8 warps (1x4? no: 2x4 as before -> warpM 0..1, warpN 0..3),
// occ 2, K chunk 64, 3 stages.  B tile stored as two [64k x 64n] subtiles,
// consumed via ldmatrix.trans (mapping identical to the verified PV path).
// OUT_MODE 0: QKV -- weight selected by blockIdx.x>>3, n0=(blockIdx.x&7)*128
// OUT_MODE 3: out-proj -- B param, n0 = blockIdx.x*128, fp32 out + bias
// ============================================================================
#define GSTAGE 32768
#define GEMM_SMEM (3 * GSTAGE)

template<int OUT_MODE>
__global__ __launch_bounds__(256, 2)
void gemm_mma(const half* __restrict__ A, const half* __restrict__ Bp,
              const float* __restrict__ bias, float* __restrict__ out)
{
    extern __shared__ char sm[];
    const uint32_t sbase = smem_u32(sm);

    const int tid   = threadIdx.x;
    const int wid   = tid >> 5;
    const int lane  = tid & 31;
    const int warpM = wid >> 2;        // 0..1
    const int warpN = wid & 3;         // 0..3
    const int bm = blockIdx.y * 128;

    int wsel, n0;
    const half* B;
    if (OUT_MODE == 0) {
        wsel = blockIdx.x >> 3;
        n0   = (blockIdx.x & 7) * 128;
        B    = g_w + (size_t)wsel * 1024 * 1024;
    } else {
        wsel = 0;
        n0   = blockIdx.x * 128;
        B    = Bp;
    }

    // staging per stage: A[128m x 64k] 16K  |  B two subtiles [64k x 64n] 16K
    const half* gsA[4];  uint32_t sdA[4];
    const half* gsB[4];  uint32_t sdB[4];
#pragma unroll
    for (int i = 0; i < 4; i++) {
        int idx = i * 256 + tid;          // 0..1023
        {   // A chunk: r = m-row, c = k-chunk
            int r = idx >> 3, c = idx & 7;
            gsA[i] = A + (size_t)(bm + r) * 1024 + c * 8;
            sdA[i] = sbase + asw(r, c);
        }
        {   // B chunk: h = n-half, rr = k-row, cc = n-chunk(16B)
            int h = idx >> 9, t = idx & 511;
            int rr = t >> 3, cc = t & 7;
            gsB[i] = B + (size_t)rr * 1024 + n0 + h * 64 + cc * 8;
            sdB[i] = sbase + 16384 + h * 8192 + asw(rr, cc);
        }
    }

    float acc[4][4][4];
#pragma unroll
    for (int mt = 0; mt < 4; mt++)
#pragma unroll
        for (int nt = 0; nt < 4; nt++)
#pragma unroll
            for (int k = 0; k < 4; k++) acc[mt][nt][k] = 0.f;

#pragma unroll
    for (int s = 0; s < 2; s++) {
#pragma unroll
        for (int i = 0; i < 4; i++) {
            CP_ASYNC16(sdA[i] + s * GSTAGE, gsA[i] + s * 64);
            CP_ASYNC16(sdB[i] + s * GSTAGE, gsB[i] + (size_t)s * 64 * 1024);
        }
        CP_COMMIT();
    }

    const int mrow = warpM * 64 + (lane & 7) + ((lane >> 3) & 1) * 8;
    const int bsub = warpN >> 1;              // B subtile for this warp
    const int brow = (lane & 7) + ((lane >> 3) & 1) * 8;   // + ks*16
    const int bcol0 = (warpN & 1) * 4 + (lane >> 4);       // + p*2

    for (int kt = 0; kt < 16; kt++) {
        if (kt == 15) { CP_WAIT(0); } else { CP_WAIT(1); }
        __syncthreads();
        if (kt + 2 < 16) {
            int st = (kt + 2) % 3;
#pragma unroll
            for (int i = 0; i < 4; i++) {
                CP_ASYNC16(sdA[i] + st * GSTAGE, gsA[i] + (kt + 2) * 64);
                CP_ASYNC16(sdB[i] + st * GSTAGE, gsB[i] + (size_t)(kt + 2) * 64 * 1024);
            }
            CP_COMMIT();
        }

        const uint32_t s0 = sbase + (kt % 3) * GSTAGE;
        const uint32_t sB = s0 + 16384 + bsub * 8192;
#pragma unroll
        for (int ks = 0; ks < 4; ks++) {
            uint32_t aS[4][4], bb[2][4];
            const int ac = ks * 2 + (lane >> 4);
#pragma unroll
            for (int mt = 0; mt < 4; mt++) {
                int m = mrow + mt * 16;
                ldsm4(aS[mt], s0 + asw(m, ac));
            }
#pragma unroll
            for (int p = 0; p < 2; p++) {
                ldsm4t(bb[p], sB + asw(ks * 16 + brow, bcol0 + p * 2));
            }
#pragma unroll
            for (int mt = 0; mt < 4; mt++)
#pragma unroll
                for (int p = 0; p < 2; p++) {
                    mma16816(acc[mt][2 * p],     aS[mt], bb[p]);
                    mma16816(acc[mt][2 * p + 1], aS[mt], bb[p] + 2);
                }
        }
    }

    // ---- epilogue ----
#pragma unroll
    for (int mt = 0; mt < 4; mt++) {
#pragma unroll
        for (int nt = 0; nt < 4; nt++) {
            int r0 = bm + warpM * 64 + mt * 16 + (lane >> 2);
            int nl = n0 + warpN * 32 + nt * 8 + (lane & 3) * 2;   // n within 1024
#pragma unroll
            for (int half_ = 0; half_ < 2; half_++) {
                int r = r0 + half_ * 8;
                float v0 = acc[mt][nt][half_ * 2 + 0];
                float v1 = acc[mt][nt][half_ * 2 + 1];
                if (OUT_MODE == 3) {
                    v0 += bias[nl];
                    v1 += bias[nl + 1];
                    *(float2*)(out + (size_t)r * 1024 + nl) = make_float2(v0, v1);
                } else {
                    v0 += bias[wsel * 1024 + nl];
                    v1 += bias[wsel * 1024 + nl + 1];
                    int b = r >> 11, s = r & 2047;
                    int h = nl >> 6;
                    int d = nl & 63;
                    size_t idx = (((size_t)(b * NH + h)) * SEQ + s) * HD + d;
                    half* dst = (wsel == 0) ? g_q : (wsel == 1) ? g_k : g_v;
                    *(uint32_t*)(dst + idx) = packh(v1, v0);
                }
            }
        }
    }
}

// ============================================================================
// HMMA fp16 flash attention (R12 structure: fp32 acc, 4-stage, 1 barrier / 2)
// ============================================================================
#define ASTGSZ 16384
#define AQ     (3 * ASTGSZ)
#define AQREL  65536
#define ATV    70144
#define ATK    72448
#define ATTN_SMEM 74752

__global__ __launch_bounds__(256, 2)
void attn_mma(const float* __restrict__ tkg, const float* __restrict__ tvg)
{
    extern __shared__ char sm[];
    const uint32_t sb = smem_u32(sm);
    float* qrel_s = (float*)(sm + AQREL);
    float* tv_s   = (float*)(sm + ATV);
    float* tk_s   = (float*)(sm + ATK);

    const int tid  = threadIdx.x;
    const int lane = tid & 31;
    const int w    = tid >> 5;
    const int bh   = blockIdx.y;
    const int q0   = blockIdx.x * 128;
    const size_t bhoff = (size_t)bh * SEQ * HD;

#pragma unroll
    for (int i = 0; i < 4; i++) {
        int g = i * 256 + tid;
        int r = g >> 3, c = g & 7;
        CP_ASYNC16(sb + AQ + asw(r, c), g_q + bhoff + (size_t)(q0 + r) * HD + c * 8);
    }
    CP_COMMIT();
#pragma unroll
    for (int st = 0; st < 2; st++) {
#pragma unroll
        for (int i = 0; i < 4; i++) {
            int g = i * 256 + tid;
            int tile = g >> 9;
            int idx = g & 511;
            int r = idx >> 3, c = idx & 7;
            const half* src = (tile == 0 ? g_k : g_v)
                + bhoff + (size_t)(st * 64 + r) * HD + c * 8;
            CP_ASYNC16(sb + st * ASTGSZ + tile * 8192 + asw(r, c), src);
        }
        CP_COMMIT();
    }
    for (int i = tid; i < NR * 64; i += 256) { tk_s[i] = tkg[i]; tv_s[i] = tvg[i]; }

    CP_WAIT(2);
    __syncthreads();

    if (tid < 128) {
        int row = tid;
        float acc[NR];
#pragma unroll
        for (int r9 = 0; r9 < NR; r9++) acc[r9] = 0.f;
        for (int d = 0; d < 64; d++) {
            float q = __half2float(*(const half*)(sm + AQ + asw(row, d >> 3) + (d & 7) * 2));
#pragma unroll
            for (int r9 = 0; r9 < NR; r9++) acc[r9] += q * tk_s[r9 * 64 + d];
        }
#pragma unroll
        for (int r9 = 0; r9 < NR; r9++) qrel_s[row * NR + r9] = acc[r9];
    }
    __syncthreads();

    uint32_t qf[4][4];
#pragma unroll
    for (int ks = 0; ks < 4; ks++) {
        int r = w * 16 + (lane & 7) + ((lane >> 3) & 1) * 8;
        int c = ks * 2 + (lane >> 4);
        ldsm4(qf[ks], sb + AQ + asw(r, c));
    }

    const int row0 = w * 16 + (lane >> 2);
    const int row1 = row0 + 8;
    const float qA0 = qrel_s[row0 * NR + 0], qA8 = qrel_s[row0 * NR + 8];
    const float qB0 = qrel_s[row1 * NR + 0], qB8 = qrel_s[row1 * NR + 8];

    float oacc[8][4];
#pragma unroll
    for (int nt = 0; nt < 8; nt++)
#pragma unroll
        for (int e = 0; e < 4; e++) oacc[nt][e] = 0.f;
    float brA[NR], brB[NR];
#pragma unroll
    for (int r9 = 0; r9 < NR; r9++) { brA[r9] = 0.f; brB[r9] = 0.f; }

    for (int j = 0; j < 16; j++) {
        __syncthreads();

        if (j < 15) {
#pragma unroll
            for (int t2 = 0; t2 < 2; t2++) {
                int t = 2 * j + 2 + t2;
                uint32_t stb = sb + (t & 3) * ASTGSZ;
#pragma unroll
                for (int i = 0; i < 4; i++) {
                    int g = i * 256 + tid;
                    int tile = g >> 9;
                    int idx = g & 511;
                    int r = idx >> 3, c = idx & 7;
                    const half* src = (tile == 0 ? g_k : g_v)
                        + bhoff + (size_t)(t * 64 + r) * HD + c * 8;
                    CP_ASYNC16(stb + tile * 8192 + asw(r, c), src);
                }
                CP_COMMIT();
            }
            CP_WAIT(2);
        } else {
            CP_WAIT(0);
        }

#pragma unroll
        for (int t2 = 0; t2 < 2; t2++) {
            const int kt = 2 * j + t2;
            const uint32_t stg = sb + (kt & 3) * ASTGSZ;

            float sacc[8][4];
#pragma unroll
            for (int nt = 0; nt < 8; nt++)
#pragma unroll
                for (int e = 0; e < 4; e++) sacc[nt][e] = 0.f;

#pragma unroll
            for (int ks = 0; ks < 4; ks++) {
#pragma unroll
                for (int ntp = 0; ntp < 4; ntp++) {
                    uint32_t bK[4];
                    int r = ntp * 16 + (lane & 7) + ((lane >> 4) << 3);
                    int c = ks * 2 + ((lane >> 3) & 1);
                    ldsm4(bK, stg + asw(r, c));
                    mma16816(sacc[2 * ntp],     qf[ks], bK);
                    mma16816(sacc[2 * ntp + 1], qf[ks], bK + 2);
                }
            }

            const int k64 = kt * 64;
            bool hi_far = (k64 >= q0 + 131);
            bool lo_far = (k64 + 67 <= q0);
            if (hi_far || lo_far) {
                float biasA = hi_far ? qA8 : qA0;
                float biasB = hi_far ? qB8 : qB0;
                float sA = 0.f, sB = 0.f;
#pragma unroll
                for (int nt = 0; nt < 8; nt++) {
#pragma unroll
                    for (int e = 0; e < 4; e++) {
                        float p = __expf((sacc[nt][e] + (e < 2 ? biasA : biasB)) * 0.125f);
                        sacc[nt][e] = p;
                        if (e < 2) sA += p; else sB += p;
                    }
                }
                if (hi_far) { brA[8] += sA; brB[8] += sB; }
                else        { brA[0] += sA; brB[0] += sB; }
            } else {
#pragma unroll
                for (int nt = 0; nt < 8; nt++) {
#pragma unroll
                    for (int e = 0; e < 4; e++) {
                        int row = (e < 2) ? row0 : row1;
                        int col = nt * 8 + ((lane & 3) << 1) + (e & 1);
                        int rel = k64 + col - (q0 + row);
                        int bucket = min(max(rel, -4), 4) + 4;
                        float p = __expf((sacc[nt][e] + qrel_s[row * NR + bucket]) * 0.125f);
                        sacc[nt][e] = p;
                        float* br = (e < 2) ? brA : brB;
#pragma unroll
                        for (int r9 = 0; r9 < NR; r9++)
                            br[r9] += (bucket == r9) ? p : 0.f;
                    }
                }
            }

            uint32_t pf[4][4];
#pragma unroll
            for (int ks = 0; ks < 4; ks++) {
#pragma unroll
                for (int t = 0; t < 2; t++) {
                    pf[ks][2 * t]     = packh(sacc[2 * ks + t][1], sacc[2 * ks + t][0]);
                    pf[ks][2 * t + 1] = packh(sacc[2 * ks + t][3], sacc[2 * ks + t][2]);
                }
            }

#pragma unroll
            for (int ks = 0; ks < 4; ks++) {
#pragma unroll
                for (int ntp = 0; ntp < 4; ntp++) {
                    uint32_t vS[4];
                    int r = ks * 16 + (lane & 7) + ((lane >> 3) & 1) * 8;
                    int c = ntp * 2 + (lane >> 4);
                    ldsm4t(vS, stg + 8192 + asw(r, c));
                    mma16816(oacc[2 * ntp],     pf[ks], vS);
                    mma16816(oacc[2 * ntp + 1], pf[ks], vS + 2);
                }
            }
        }
    }

#pragma unroll
    for (int m = 1; m <= 2; m <<= 1) {
#pragma unroll
        for (int r9 = 0; r9 < NR; r9++) {
            brA[r9] += __shfl_xor_sync(0xffffffffu, brA[r9], m);
            brB[r9] += __shfl_xor_sync(0xffffffffu, brB[r9], m);
        }
    }
    float lA = 0.f, lB = 0.f;
#pragma unroll
    for (int r9 = 0; r9 < NR; r9++) { lA += brA[r9]; lB += brB[r9]; }
    const float iA = 1.f / lA, iB = 1.f / lB;

    const int b = bh >> 4, h = bh & 15;
    const size_t m0 = (size_t)(b * SEQ + q0 + row0) * HID + h * 64;
    const size_t m1 = (size_t)(b * SEQ + q0 + row1) * HID + h * 64;

#pragma unroll
    for (int nt = 0; nt < 8; nt++) {
        int d0 = nt * 8 + (lane & 3) * 2;
        float w00 = 0.f, w01 = 0.f, w10 = 0.f, w11 = 0.f;
#pragma unroll
        for (int r9 = 0; r9 < NR; r9++) {
            float2 t2 = *(const float2*)(tv_s + r9 * 64 + d0);
            w00 += brA[r9] * t2.x; w01 += brA[r9] * t2.y;
            w10 += brB[r9] * t2.x; w11 += brB[r9] * t2.y;
        }
        float v00 = (oacc[nt][0] + w00) * iA, v01 = (oacc[nt][1] + w01) * iA;
        float v10 = (oacc[nt][2] + w10) * iB, v11 = (oacc[nt][3] + w11) * iB;

        *(uint32_t*)(g_c + m0 + d0) = packh(v01, v00);
        *(uint32_t*)(g_c + m1 + d0) = packh(v11, v10);
    }
}

// ============================================================================
extern "C" void kernel_launch(void* const* d_in, const int* in_sizes, int n_in,
                              void* d_out, int out_size)
{
    const float* x  = (const float*)d_in[0];
    const float* Wq = (const float*)d_in[1];
    const float* bq = (const float*)d_in[2];
    const float* Wk = (const float*)d_in[3];
    const float* bk = (const float*)d_in[4];
    const float* Wv = (const float*)d_in[5];
    const float* bv = (const float*)d_in[6];
    const float* Wo = (const float*)d_in[7];
    const float* bo = (const float*)d_in[8];
    const float* tk = (const float*)d_in[9];
    const float* tv = (const float*)d_in[10];
    float* out = (float*)d_out;

    half *xf, *cc, *wo;
    float* bcat;
    cudaGetSymbolAddress((void**)&xf,  g_xf);
    cudaGetSymbolAddress((void**)&cc,  g_c);
    cudaGetSymbolAddress((void**)&wo,  g_wo);
    cudaGetSymbolAddress((void**)&bcat, g_bcat);

    cudaFuncSetAttribute(gemm_mma<0>, cudaFuncAttributeMaxDynamicSharedMemorySize, GEMM_SMEM);
    cudaFuncSetAttribute(gemm_mma<3>, cudaFuncAttributeMaxDynamicSharedMemorySize, GEMM_SMEM);
    cudaFuncSetAttribute(attn_mma,    cudaFuncAttributeMaxDynamicSharedMemorySize, ATTN_SMEM);

    // 1. fused prep (pure streaming convert, no transpose)
    prep_all<<<2049, 256>>>(x, Wq, Wk, Wv, Wo, bq, bk, bv);

    // 2. fused QKV projection (blockIdx.x: 0..23 -> weight w = x>>3, n0 = (x&7)*128)
    gemm_mma<0><<<dim3(24, 32), 256, GEMM_SMEM>>>(xf, nullptr, bcat, nullptr);

    // 3. flash attention
    attn_mma<<<dim3(SEQ / 128, Bsz * NH), 256, ATTN_SMEM>>>(tk, tv);

    // 4. output projection
    gemm_mma<3><<<dim3(8, 32), 256, GEMM_SMEM>>>(cc, wo, bo, out);
}